// round 6
// baseline (speedup 1.0000x reference)
#include <cuda_runtime.h>
#include <cstdint>

// PrototypeLoss: loss = 1 - (1/B) * sum_c || sum_{i: label_i=c} normalize(f_i) ||
// B = 262144, D = 256, C = 1000 (fixed shapes)
//
// Two graph nodes:
//   scatter_kernel : 1 label/thread bucket scatter (single atomic per thread).
//   class_kernel   : NSEG=4 segment blocks per class; indices staged in smem;
//                    4-row-unrolled gather+normalize; partial class sums merged
//                    via float RED.ADD; per-class ticket elects norm finisher;
//                    global ticket elects output writer. All state self-resets
//                    (graph-replayable, __device__ globals zeroed at load).

static constexpr int C_CLS = 1000;
static constexpr int D_DIM = 256;
static constexpr int CAP   = 1024;   // bucket capacity (expected ~262/class)
static constexpr int NSEG  = 4;      // segment blocks per class
static constexpr int SEGCAP = CAP / NSEG;  // 256 entries max per segment

__device__ int      g_cnt[C_CLS];          // reset by finisher
__device__ int      g_idx[C_CLS * CAP];
__device__ float    g_sum[C_CLS * D_DIM];  // reset by finisher
__device__ int      g_cdone[C_CLS];
__device__ float    g_acc;
__device__ unsigned g_done;

// ---------------------------------------------------------------------------
// Scatter: one label per thread, one atomic per thread.
// int64-vs-int32 probe: LE int64 labels in [0,1000) have all odd 32-bit words
// zero; 64 random int32 labels all-zero has probability ~1e-192. Probed words
// lie in the first 1KB (valid under either dtype).
// ---------------------------------------------------------------------------
__global__ __launch_bounds__(512) void scatter_kernel(const void* __restrict__ labels,
                                                      int B) {
    __shared__ int s_is64;
    const int* lbl32 = (const int*)labels;
    if (threadIdx.x < 32) {
        int v = lbl32[2 * threadIdx.x + 1] | lbl32[2 * threadIdx.x + 65];
        unsigned any = __ballot_sync(0xffffffffu, v != 0);
        if (threadIdx.x == 0) s_is64 = (any == 0u) ? 1 : 0;
    }
    __syncthreads();

    int i = blockIdx.x * 512 + threadIdx.x;
    if (i >= B) return;
    int l = s_is64 ? (int)((const long long*)labels)[i] : lbl32[i];
    if ((unsigned)l >= (unsigned)C_CLS) return;   // defensive
    int p = atomicAdd(&g_cnt[l], 1);
    if (p < CAP) g_idx[l * CAP + p] = i;
}

// ---------------------------------------------------------------------------
// class_kernel: block b -> class c = b/NSEG, segment s = b%NSEG.
// Stage 1: segment's indices (entries e = s + NSEG*t) -> smem (coalesced).
// Stage 2: warp w processes staged entries w, w+8, ... ; unroll 4 rows
//          (16 outstanding LDG.128, 4 interleaved shuffle chains).
// Stage 3: cross-warp combine -> 256 float RED.ADD into g_sum[c].
// Stage 4: last segment of class computes ||g_sum[c]||, scalar atomic;
//          last class overall writes out[0].
// ---------------------------------------------------------------------------
__global__ __launch_bounds__(256) void class_kernel(const float* __restrict__ f,
                                                    float* __restrict__ out,
                                                    int B) {
    __shared__ int   s_idx[SEGCAP];
    __shared__ float sm[8][8][33];   // [warp][slot][lane], padded
    __shared__ int   s_fin;
    __shared__ float s_red[8];

    const int b   = blockIdx.x;
    const int c   = b >> 2;          // NSEG == 4
    const int seg = b & 3;
    int n = g_cnt[c];
    if (n > CAP) n = CAP;
    const int warp = threadIdx.x >> 5;
    const int lane = threadIdx.x & 31;

    // entries e = seg + 4*t, e < n
    const int n_seg = (n > seg) ? ((n - seg + NSEG - 1) >> 2) : 0;
    const int* __restrict__ idx = &g_idx[c * CAP];
    for (int t = threadIdx.x; t < n_seg; t += 256)
        s_idx[t] = idx[seg + (t << 2)];
    __syncthreads();

    float a0 = 0.f, a1 = 0.f, a2 = 0.f, a3 = 0.f;
    float a4 = 0.f, a5 = 0.f, a6 = 0.f, a7 = 0.f;

    int t = warp;
    for (; t + 24 < n_seg; t += 32) {
        int r0 = s_idx[t];
        int r1 = s_idx[t + 8];
        int r2 = s_idx[t + 16];
        int r3 = s_idx[t + 24];
        const float4* __restrict__ p0 = (const float4*)(f + (size_t)r0 * D_DIM);
        const float4* __restrict__ p1 = (const float4*)(f + (size_t)r1 * D_DIM);
        const float4* __restrict__ p2 = (const float4*)(f + (size_t)r2 * D_DIM);
        const float4* __restrict__ p3 = (const float4*)(f + (size_t)r3 * D_DIM);
        float4 x0 = p0[lane], y0 = p0[lane + 32];
        float4 x1 = p1[lane], y1 = p1[lane + 32];
        float4 x2 = p2[lane], y2 = p2[lane + 32];
        float4 x3 = p3[lane], y3 = p3[lane + 32];
        float s0 = x0.x*x0.x + x0.y*x0.y + x0.z*x0.z + x0.w*x0.w
                 + y0.x*y0.x + y0.y*y0.y + y0.z*y0.z + y0.w*y0.w;
        float s1 = x1.x*x1.x + x1.y*x1.y + x1.z*x1.z + x1.w*x1.w
                 + y1.x*y1.x + y1.y*y1.y + y1.z*y1.z + y1.w*y1.w;
        float s2 = x2.x*x2.x + x2.y*x2.y + x2.z*x2.z + x2.w*x2.w
                 + y2.x*y2.x + y2.y*y2.y + y2.z*y2.z + y2.w*y2.w;
        float s3 = x3.x*x3.x + x3.y*x3.y + x3.z*x3.z + x3.w*x3.w
                 + y3.x*y3.x + y3.y*y3.y + y3.z*y3.z + y3.w*y3.w;
        #pragma unroll
        for (int o = 16; o; o >>= 1) {
            s0 += __shfl_xor_sync(0xffffffffu, s0, o);
            s1 += __shfl_xor_sync(0xffffffffu, s1, o);
            s2 += __shfl_xor_sync(0xffffffffu, s2, o);
            s3 += __shfl_xor_sync(0xffffffffu, s3, o);
        }
        float i0 = rsqrtf(fmaxf(s0, 1e-24f));
        float i1 = rsqrtf(fmaxf(s1, 1e-24f));
        float i2 = rsqrtf(fmaxf(s2, 1e-24f));
        float i3 = rsqrtf(fmaxf(s3, 1e-24f));
        a0 += x0.x*i0 + x1.x*i1 + x2.x*i2 + x3.x*i3;
        a1 += x0.y*i0 + x1.y*i1 + x2.y*i2 + x3.y*i3;
        a2 += x0.z*i0 + x1.z*i1 + x2.z*i2 + x3.z*i3;
        a3 += x0.w*i0 + x1.w*i1 + x2.w*i2 + x3.w*i3;
        a4 += y0.x*i0 + y1.x*i1 + y2.x*i2 + y3.x*i3;
        a5 += y0.y*i0 + y1.y*i1 + y2.y*i2 + y3.y*i3;
        a6 += y0.z*i0 + y1.z*i1 + y2.z*i2 + y3.z*i3;
        a7 += y0.w*i0 + y1.w*i1 + y2.w*i2 + y3.w*i3;
    }
    for (; t < n_seg; t += 8) {
        int r = s_idx[t];
        const float4* __restrict__ p = (const float4*)(f + (size_t)r * D_DIM);
        float4 x = p[lane], y = p[lane + 32];
        float s = x.x*x.x + x.y*x.y + x.z*x.z + x.w*x.w
                + y.x*y.x + y.y*y.y + y.z*y.z + y.w*y.w;
        #pragma unroll
        for (int o = 16; o; o >>= 1) s += __shfl_xor_sync(0xffffffffu, s, o);
        float iv = rsqrtf(fmaxf(s, 1e-24f));
        a0 += x.x*iv; a1 += x.y*iv; a2 += x.z*iv; a3 += x.w*iv;
        a4 += y.x*iv; a5 += y.y*iv; a6 += y.z*iv; a7 += y.w*iv;
    }

    // lane l, slot k (0-3) -> element 4l+k ; slots 4-7 -> element 128+4l+k
    sm[warp][0][lane] = a0; sm[warp][1][lane] = a1;
    sm[warp][2][lane] = a2; sm[warp][3][lane] = a3;
    sm[warp][4][lane] = a4; sm[warp][5][lane] = a5;
    sm[warp][6][lane] = a6; sm[warp][7][lane] = a7;
    __syncthreads();

    // thread t -> element t; combine 8 warps; one RED.ADD
    {
        int e    = threadIdx.x;
        int lo   = (e < 128) ? e : (e - 128);
        int slot = ((e < 128) ? 0 : 4) + (lo & 3);
        int l    = lo >> 2;
        float v = 0.f;
        #pragma unroll
        for (int w = 0; w < 8; w++) v += sm[w][slot][l];
        atomicAdd(&g_sum[c * D_DIM + e], v);
    }

    __threadfence();
    __syncthreads();
    if (threadIdx.x == 0) {
        int p = atomicAdd(&g_cdone[c], 1);
        s_fin = (p == NSEG - 1) ? 1 : 0;
    }
    __syncthreads();

    if (s_fin) {
        __threadfence();
        int e = threadIdx.x;
        volatile float* gs = g_sum;
        float v = gs[c * D_DIM + e];
        g_sum[c * D_DIM + e] = 0.f;            // self-reset
        float ss = v * v;
        #pragma unroll
        for (int o = 16; o; o >>= 1) ss += __shfl_xor_sync(0xffffffffu, ss, o);
        if (lane == 0) s_red[warp] = ss;
        __syncthreads();
        if (threadIdx.x == 0) {
            float tot = 0.f;
            #pragma unroll
            for (int w = 0; w < 8; w++) tot += s_red[w];
            atomicAdd(&g_acc, sqrtf(tot));
            g_cnt[c]   = 0;                    // self-reset
            g_cdone[c] = 0;
            __threadfence();
            unsigned q = atomicAdd(&g_done, 1u);
            if (q == (unsigned)(C_CLS - 1)) {
                __threadfence();
                float acc = *((volatile float*)&g_acc);
                out[0] = 1.0f - acc / (float)B;
                g_acc  = 0.0f;
                g_done = 0u;
            }
        }
    }
}

extern "C" void kernel_launch(void* const* d_in, const int* in_sizes, int n_in,
                              void* d_out, int out_size) {
    const float* features = (const float*)d_in[0];
    const void*  labels   = d_in[1];
    int B = in_sizes[1];                                    // 262144 labels
    if (B * D_DIM != in_sizes[0]) B = in_sizes[0] / D_DIM;  // defensive

    scatter_kernel<<<(B + 511) / 512, 512>>>(labels, B);
    class_kernel<<<C_CLS * NSEG, 256>>>(features, (float*)d_out, B);
}